// round 17
// baseline (speedup 1.0000x reference)
#include <cuda_runtime.h>
#include <cuda_bf16.h>
#include <cstdint>

// Problem constants
#define HNUM 12
#define PDIM 64
#define DDIM 768
#define NSEQ 1024
#define MAXB 8
#define KCAT (3 * DDIM)
#define NCH (KCAT / 64)

// proj GEMM smem
#define GEMM_SMEM (128 * 132 * 4 + 1024)

// attn smem layout (byte offsets into dynamic smem)
#define O_QHI 0
#define O_QLO 16384
#define O_KHI 32768
#define O_KLO 49152
#define O_VHI 65536
#define O_VLO 81920
#define O_EHI 98304
#define O_ELO 131072
#define O_PST 163840        // per-warp fp32 16x44 stage (aliases PHI/PLO; sync-separated)
#define O_PHI 163840
#define O_PLO 196608
#define O_RED 229376        // fp32 [128][2] cross-warp max/sum exchange
#define ATTN_SMEM 230400

// Device scratch
__device__ __nv_bfloat16 g_qhi[MAXB * HNUM * NSEQ * PDIM];
__device__ __nv_bfloat16 g_qlo[MAXB * HNUM * NSEQ * PDIM];
__device__ __nv_bfloat16 g_khi[MAXB * HNUM * NSEQ * PDIM];
__device__ __nv_bfloat16 g_klo[MAXB * HNUM * NSEQ * PDIM];
__device__ __nv_bfloat16 g_vhi[MAXB * HNUM * NSEQ * PDIM];
__device__ __nv_bfloat16 g_vlo[MAXB * HNUM * NSEQ * PDIM];
__device__ __nv_bfloat16 g_ehi[2048 * PDIM];
__device__ __nv_bfloat16 g_elo[2048 * PDIM];
__device__ __nv_bfloat16 g_xcat[MAXB * NSEQ * KCAT];
__device__ __nv_bfloat16 g_wcat[3 * DDIM * KCAT];

// ---------------------------------------------------------------------------
// PTX helpers
// ---------------------------------------------------------------------------
__device__ __forceinline__ uint32_t smaddr(const void* p) {
    return (uint32_t)__cvta_generic_to_shared(p);
}
__device__ __forceinline__ void cp16(uint32_t dst, const void* src) {
    asm volatile("cp.async.cg.shared.global [%0], [%1], 16;" :: "r"(dst), "l"(src));
}
__device__ __forceinline__ void cp_commit() {
    asm volatile("cp.async.commit_group;" ::: "memory");
}
__device__ __forceinline__ void cp_wait0() {
    asm volatile("cp.async.wait_group 0;" ::: "memory");
}
__device__ __forceinline__ void cp_wait1() {
    asm volatile("cp.async.wait_group 1;" ::: "memory");
}
__device__ __forceinline__ void cp_wait2() {
    asm volatile("cp.async.wait_group 2;" ::: "memory");
}
__device__ __forceinline__ void ldm_x4(uint32_t* r, uint32_t a) {
    asm volatile("ldmatrix.sync.aligned.m8n8.x4.shared.b16 {%0,%1,%2,%3}, [%4];"
                 : "=r"(r[0]), "=r"(r[1]), "=r"(r[2]), "=r"(r[3]) : "r"(a));
}
__device__ __forceinline__ void ldm_x4t(uint32_t* r, uint32_t a) {
    asm volatile("ldmatrix.sync.aligned.m8n8.x4.trans.shared.b16 {%0,%1,%2,%3}, [%4];"
                 : "=r"(r[0]), "=r"(r[1]), "=r"(r[2]), "=r"(r[3]) : "r"(a));
}
__device__ __forceinline__ void mma_bf16(float* c, const uint32_t* a,
                                         uint32_t b0, uint32_t b1) {
    asm volatile(
        "mma.sync.aligned.m16n8k16.row.col.f32.bf16.bf16.f32 "
        "{%0,%1,%2,%3}, {%4,%5,%6,%7}, {%8,%9}, {%0,%1,%2,%3};"
        : "+f"(c[0]), "+f"(c[1]), "+f"(c[2]), "+f"(c[3])
        : "r"(a[0]), "r"(a[1]), "r"(a[2]), "r"(a[3]), "r"(b0), "r"(b1));
}
__device__ __forceinline__ uint32_t pack_bf16x2(float a, float b) {
    __nv_bfloat16 ha = __float2bfloat16(a), hb = __float2bfloat16(b);
    return ((uint32_t)__bfloat16_as_ushort(hb) << 16) | __bfloat16_as_ushort(ha);
}

// ---------------------------------------------------------------------------
// Split kernels
// ---------------------------------------------------------------------------
__device__ __forceinline__ void split_store(
    float4 v, __nv_bfloat16* dst, size_t base, int hi2_off, int lo_off)
{
    float hx = __bfloat162float(__float2bfloat16(v.x));
    float hy = __bfloat162float(__float2bfloat16(v.y));
    float hz = __bfloat162float(__float2bfloat16(v.z));
    float hw = __bfloat162float(__float2bfloat16(v.w));
    uint2 hi, lo;
    hi.x = pack_bf16x2(v.x, v.y);
    hi.y = pack_bf16x2(v.z, v.w);
    lo.x = pack_bf16x2(v.x - hx, v.y - hy);
    lo.y = pack_bf16x2(v.z - hz, v.w - hw);
    *(uint2*)(dst + base)           = hi;
    *(uint2*)(dst + base + hi2_off) = hi;
    *(uint2*)(dst + base + lo_off)  = lo;
}

__global__ __launch_bounds__(256) void xsplit_kernel(
    const float* __restrict__ src, __nv_bfloat16* __restrict__ dst, int n4)
{
    int i = blockIdx.x * 256 + threadIdx.x;
    if (i >= n4) return;
    int row = i / (DDIM / 4);
    int c4  = i - row * (DDIM / 4);
    float4 v = ((const float4*)src)[i];
    // x layout: [hi | lo | hi]
    split_store(v, dst, (size_t)row * KCAT + c4 * 4, 2 * DDIM, DDIM);
}

__global__ __launch_bounds__(256) void wsplit_kernel(
    const float* __restrict__ wq, const float* __restrict__ wk,
    const float* __restrict__ wv, __nv_bfloat16* __restrict__ wcat)
{
    int z = blockIdx.y;
    const float* src = (z == 0) ? wq : (z == 1) ? wk : wv;
    __nv_bfloat16* dst = wcat + (size_t)z * DDIM * KCAT;
    int i = blockIdx.x * 256 + threadIdx.x;
    if (i >= DDIM * (DDIM / 4)) return;
    int row = i / (DDIM / 4);
    int c4  = i - row * (DDIM / 4);
    float4 v = ((const float4*)src)[i];
    // w layout: [hi | hi | lo]
    split_store(v, dst, (size_t)row * KCAT + c4 * 4, DDIM, 2 * DDIM);
}

__global__ __launch_bounds__(256) void esplit_kernel(
    const float* __restrict__ de, __nv_bfloat16* __restrict__ ehi,
    __nv_bfloat16* __restrict__ elo)
{
    int i = blockIdx.x * 256 + threadIdx.x;
    if (i >= 2048 * 16) return;
    int row = i >> 4, c4 = i & 15;
    float4 v = (row < 2047) ? ((const float4*)de)[row * 16 + c4]
                            : make_float4(0.f, 0.f, 0.f, 0.f);
    float hx = __bfloat162float(__float2bfloat16(v.x));
    float hy = __bfloat162float(__float2bfloat16(v.y));
    float hz = __bfloat162float(__float2bfloat16(v.z));
    float hw = __bfloat162float(__float2bfloat16(v.w));
    uint2 hi, lo;
    hi.x = pack_bf16x2(v.x, v.y);
    hi.y = pack_bf16x2(v.z, v.w);
    lo.x = pack_bf16x2(v.x - hx, v.y - hy);
    lo.y = pack_bf16x2(v.z - hz, v.w - hw);
    size_t o = (size_t)row * PDIM + c4 * 4;
    *(uint2*)(ehi + o) = hi;
    *(uint2*)(elo + o) = lo;
}

// ---------------------------------------------------------------------------
// HMMA projection GEMM (unchanged from R16).
// ---------------------------------------------------------------------------
__global__ __launch_bounds__(256) void gemm_kernel(
    const __nv_bfloat16* __restrict__ Xc, const __nv_bfloat16* __restrict__ Wc,
    const float* __restrict__ bq, const float* __restrict__ bk,
    const float* __restrict__ bv,
    __nv_bfloat16* __restrict__ qhi, __nv_bfloat16* __restrict__ qlo,
    __nv_bfloat16* __restrict__ khi, __nv_bfloat16* __restrict__ klo,
    __nv_bfloat16* __restrict__ vhi, __nv_bfloat16* __restrict__ vlo)
{
    extern __shared__ char smraw[];

    const int tid = threadIdx.x;
    const int wid = tid >> 5;
    const int lid = tid & 31;
    const int wr = wid >> 2;
    const int wc = wid & 3;
    const int z  = blockIdx.z;
    const int m0 = blockIdx.x * 128;
    const int n0 = blockIdx.y * 128;

    const float* bias = (z == 0) ? bq : (z == 1) ? bk : bv;
    __nv_bfloat16* ohi = (z == 0) ? qhi : (z == 1) ? khi : vhi;
    __nv_bfloat16* olo = (z == 0) ? qlo : (z == 1) ? klo : vlo;
    const float scale = (z == 0) ? 0.125f : 1.0f;

    uint32_t raw = smaddr(smraw);
    uint32_t sb  = (raw + 127) & ~127u;
    const __nv_bfloat16* Asrc = Xc + (size_t)m0 * KCAT;
    const __nv_bfloat16* Bsrc = Wc + (size_t)z * DDIM * KCAT + (size_t)n0 * KCAT;

    auto load_chunk = [&](int c, int s) {
        const int kc = c * 64;
        const uint32_t base = sb + s * 32768;
#pragma unroll
        for (int u = 0; u < 8; u++) {
            int seg = tid + u * 256;
            int isB = seg >> 10;
            int r   = (seg >> 3) & 127;
            int ch  = seg & 7;
            uint32_t dst = base + isB * 16384 + r * 128 + ((ch ^ (r & 7)) * 16);
            const __nv_bfloat16* src = (isB ? Bsrc : Asrc) +
                (size_t)r * KCAT + kc + ch * 8;
            cp16(dst, src);
        }
        cp_commit();
    };

    float acc[4][4][4];
#pragma unroll
    for (int i = 0; i < 4; i++)
#pragma unroll
        for (int j = 0; j < 4; j++)
#pragma unroll
            for (int q = 0; q < 4; q++) acc[i][j][q] = 0.f;

    const int lrow = lid & 15;
    const int lhalf = lid >> 4;
    const int lxor = lid & 7;

    load_chunk(0, 0);

    for (int c = 0; c < NCH; c++) {
        const int s = c & 1;
        if (c + 1 < NCH) { load_chunk(c + 1, s ^ 1); cp_wait1(); }
        else             { cp_wait0(); }
        __syncthreads();

        const uint32_t Abase = sb + s * 32768;
        const uint32_t Bbase = Abase + 16384;

#pragma unroll
        for (int kk = 0; kk < 4; kk++) {
            const uint32_t chsel = ((uint32_t)(2 * kk + lhalf) ^ lxor) * 16;
            uint32_t afr[4][4];
#pragma unroll
            for (int mt = 0; mt < 4; mt++)
                ldm_x4(afr[mt], Abase + (wr * 64 + mt * 16 + lrow) * 128 + chsel);
            uint32_t bfr[8];
#pragma unroll
            for (int np = 0; np < 2; np++)
                ldm_x4(bfr + np * 4, Bbase + (wc * 32 + np * 16 + lrow) * 128 + chsel);
#pragma unroll
            for (int mt = 0; mt < 4; mt++)
#pragma unroll
                for (int nt = 0; nt < 4; nt++) {
                    int np = nt >> 1, sub = nt & 1;
                    mma_bf16(acc[mt][nt], afr[mt],
                             bfr[np * 4 + sub], bfr[np * 4 + 2 + sub]);
                }
        }
        __syncthreads();
    }

    float* Dst = (float*)(smraw + (sb - raw));
#pragma unroll
    for (int mt = 0; mt < 4; mt++)
#pragma unroll
        for (int nt = 0; nt < 4; nt++) {
            int row = wr * 64 + mt * 16 + (lid >> 2);
            int col = wc * 32 + nt * 8 + 2 * (lid & 3);
            *(float2*)&Dst[row * 132 + col] =
                make_float2(acc[mt][nt][0], acc[mt][nt][1]);
            *(float2*)&Dst[(row + 8) * 132 + col] =
                make_float2(acc[mt][nt][2], acc[mt][nt][3]);
        }
    __syncthreads();

#pragma unroll
    for (int u = 0; u < 16; u++) {
        int item = tid + u * 256;
        int row = item >> 5;
        int c4  = item & 31;
        float4 d = *(const float4*)&Dst[row * 132 + c4 * 4];
        int n = n0 + c4 * 4;
        int m = m0 + row;
        int bb2 = m >> 10, il = m & 1023;
        int h = n >> 6, p = n & 63;
        float vx = (d.x + bias[n + 0]) * scale;
        float vy = (d.y + bias[n + 1]) * scale;
        float vz = (d.z + bias[n + 2]) * scale;
        float vw = (d.w + bias[n + 3]) * scale;
        float hx = __bfloat162float(__float2bfloat16(vx));
        float hy = __bfloat162float(__float2bfloat16(vy));
        float hz = __bfloat162float(__float2bfloat16(vz));
        float hw = __bfloat162float(__float2bfloat16(vw));
        uint2 hi, lo;
        hi.x = pack_bf16x2(vx, vy);
        hi.y = pack_bf16x2(vz, vw);
        lo.x = pack_bf16x2(vx - hx, vy - hy);
        lo.y = pack_bf16x2(vz - hz, vw - hw);
        size_t o = (((size_t)(bb2 * HNUM + h) * NSEQ + il) * PDIM + p);
        *(uint2*)(ohi + o) = hi;
        *(uint2*)(olo + o) = lo;
    }
}

// ---------------------------------------------------------------------------
// HMMA flash attention, 3-term bf16 split, 16 warps (8 row-strips x 2 col
// halves), per-warp 79-col bias window, cross-warp softmax via RED buffer,
// cp.async pipeline (V at top, K after QK, E after gather).
// ---------------------------------------------------------------------------
__global__ __launch_bounds__(512) void attn_kernel(
    const __nv_bfloat16* __restrict__ qhi, const __nv_bfloat16* __restrict__ qlo,
    const __nv_bfloat16* __restrict__ khi, const __nv_bfloat16* __restrict__ klo,
    const __nv_bfloat16* __restrict__ vhi, const __nv_bfloat16* __restrict__ vlo,
    const __nv_bfloat16* __restrict__ ehi, const __nv_bfloat16* __restrict__ elo,
    float* __restrict__ out)
{
    extern __shared__ char smc[];
    const uint32_t sb = smaddr(smc);

    const int tid = threadIdx.x;
    const int w   = tid >> 5;
    const int lid = tid & 31;
    const int lrow = lid & 15, lhalf = lid >> 4;
    const int lq = lid >> 2, lr4 = lid & 3;
    const int wr = w >> 1, wc = w & 1;
    const int i0 = blockIdx.x * 128;
    const int h  = blockIdx.y;
    const int bb = blockIdx.z;
    const int bh = bb * HNUM + h;

    const size_t qoff   = ((size_t)bh * NSEQ + i0) * PDIM;
    const size_t kvbase = (size_t)bh * NSEQ * PDIM;

    auto loadK = [&](int j0) {
#pragma unroll
        for (int u = 0; u < 4; u++) {
            int idx = tid + u * 512;
            int t = idx >> 10;
            int r  = (idx >> 3) & 127;
            int ch = idx & 7;
            uint32_t dst = sb + (t ? O_KLO : O_KHI) + r * 128 + ((ch ^ (r & 7)) << 4);
            cp16(dst, (t ? klo : khi) + kvbase + (size_t)(j0 + r) * PDIM + ch * 8);
        }
        cp_commit();
    };
    auto loadV = [&](int j0) {
#pragma unroll
        for (int u = 0; u < 4; u++) {
            int idx = tid + u * 512;
            int t = idx >> 10;
            int r  = (idx >> 3) & 127;
            int ch = idx & 7;
            uint32_t dst = sb + (t ? O_VLO : O_VHI) + r * 128 + ((ch ^ (r & 7)) << 4);
            cp16(dst, (t ? vlo : vhi) + kvbase + (size_t)(j0 + r) * PDIM + ch * 8);
        }
        cp_commit();
    };
    auto loadE = [&](int j0) {
        const int eb2 = i0 - j0 + 896;
#pragma unroll
        for (int u = 0; u < 8; u++) {
            int idx = tid + u * 512;
            int t = idx >> 11;
            int r  = (idx >> 3) & 255;
            int ch = idx & 7;
            uint32_t dst = sb + (t ? O_ELO : O_EHI) + r * 128 + ((ch ^ (r & 7)) << 4);
            cp16(dst, (t ? elo : ehi) + (size_t)(eb2 + r) * PDIM + ch * 8);
        }
        cp_commit();
    };

    // group G1 = Q + K(0); G2 = E(0)
#pragma unroll
    for (int u = 0; u < 4; u++) {
        int idx = tid + u * 512;
        int t = idx >> 10;
        int r  = (idx >> 3) & 127;
        int ch = idx & 7;
        uint32_t dst = sb + (t ? O_QLO : O_QHI) + r * 128 + ((ch ^ (r & 7)) << 4);
        cp16(dst, (t ? qlo : qhi) + qoff + (size_t)r * PDIM + ch * 8);
    }
    loadK(0);
    loadE(0);

    float oacc[4][4];
#pragma unroll
    for (int nt = 0; nt < 4; nt++)
#pragma unroll
        for (int q = 0; q < 4; q++) oacc[nt][q] = 0.f;
    float m_run[2] = {-1e30f, -1e30f}, l_run[2] = {0.f, 0.f};

    float* PW = (float*)(smc + O_PST) + w * 704;   // 16 x 44 fp32 per warp
    float* REDf = (float*)(smc + O_RED);           // [128][2]
    const int wbE = wr * 16 - wc * 64 + 64;        // per-warp E window base
    const uint32_t qrow_off = (uint32_t)(wr * 16 + lrow) * 128;

    for (int jt = 0; jt < 8; jt++) {
        const int j0 = jt * 128;
        __syncthreads();                   // prior PV / p reads complete
        loadV(j0);
        cp_wait2();                        // K(jt) (+Q at jt=0) complete
        __syncthreads();

        // ---- S = QK^T (3-term split), warp cols [wc*64, +64) ----
        float s[8][4];
#pragma unroll
        for (int nt = 0; nt < 8; nt++)
#pragma unroll
            for (int q = 0; q < 4; q++) s[nt][q] = 0.f;

#pragma unroll
        for (int kk = 0; kk < 4; kk++) {
            const uint32_t chsw = ((uint32_t)(2 * kk + lhalf) ^ (lrow & 7)) << 4;
            uint32_t qh4[4], ql4[4], kb[4][4];
            ldm_x4(qh4, sb + O_QHI + qrow_off + chsw);
            ldm_x4(ql4, sb + O_QLO + qrow_off + chsw);
#pragma unroll
            for (int np = 0; np < 4; np++)
                ldm_x4(kb[np], sb + O_KHI + (wc * 64 + np * 16 + lrow) * 128 + chsw);
#pragma unroll
            for (int nt = 0; nt < 8; nt++)
                mma_bf16(s[nt], qh4, kb[nt >> 1][nt & 1], kb[nt >> 1][2 + (nt & 1)]);
#pragma unroll
            for (int nt = 0; nt < 8; nt++)
                mma_bf16(s[nt], ql4, kb[nt >> 1][nt & 1], kb[nt >> 1][2 + (nt & 1)]);
#pragma unroll
            for (int np = 0; np < 4; np++)
                ldm_x4(kb[np], sb + O_KLO + (wc * 64 + np * 16 + lrow) * 128 + chsw);
#pragma unroll
            for (int nt = 0; nt < 8; nt++)
                mma_bf16(s[nt], qh4, kb[nt >> 1][nt & 1], kb[nt >> 1][2 + (nt & 1)]);
        }

        __syncthreads();                   // K smem dead
        if (jt < 7) loadK(j0 + 128);
        if (jt < 7) cp_wait2(); else cp_wait1();   // E(jt) complete
        __syncthreads();

        // ---- bias: per-warp window (79 cols), 2 chunks of 40 ----
#pragma unroll
        for (int ck = 0; ck < 2; ck++) {
            const int roff = ck * 40;
            float p[5][4];
#pragma unroll
            for (int nt = 0; nt < 5; nt++)
#pragma unroll
                for (int e = 0; e < 4; e++) p[nt][e] = 0.f;

#pragma unroll
            for (int kk = 0; kk < 4; kk++) {
                const uint32_t chsw = ((uint32_t)(2 * kk + lhalf) ^ (lrow & 7)) << 4;
                uint32_t qh4[4], ql4[4], eb[3][4];
                ldm_x4(qh4, sb + O_QHI + qrow_off + chsw);
                ldm_x4(ql4, sb + O_QLO + qrow_off + chsw);
#pragma unroll
                for (int np = 0; np < 3; np++)
                    ldm_x4(eb[np], sb + O_EHI +
                           (wbE + roff + np * 16 + lrow) * 128 + chsw);
#pragma unroll
                for (int nt = 0; nt < 5; nt++)
                    mma_bf16(p[nt], qh4, eb[nt >> 1][nt & 1], eb[nt >> 1][2 + (nt & 1)]);
#pragma unroll
                for (int nt = 0; nt < 5; nt++)
                    mma_bf16(p[nt], ql4, eb[nt >> 1][nt & 1], eb[nt >> 1][2 + (nt & 1)]);
#pragma unroll
                for (int np = 0; np < 3; np++)
                    ldm_x4(eb[np], sb + O_ELO +
                           (wbE + roff + np * 16 + lrow) * 128 + chsw);
#pragma unroll
                for (int nt = 0; nt < 5; nt++)
                    mma_bf16(p[nt], qh4, eb[nt >> 1][nt & 1], eb[nt >> 1][2 + (nt & 1)]);
            }
#pragma unroll
            for (int nt = 0; nt < 5; nt++) {
                int col = nt * 8 + 2 * lr4;
                *(float2*)&PW[lq * 44 + col] = make_float2(p[nt][0], p[nt][1]);
                *(float2*)&PW[(lq + 8) * 44 + col] = make_float2(p[nt][2], p[nt][3]);
            }
            __syncwarp();
            // diagonal gather: pwl = rl - cl + 63 in [0,78]
#pragma unroll
            for (int nt = 0; nt < 8; nt++)
#pragma unroll
                for (int idx = 0; idx < 4; idx++) {
                    int rl = lq + (idx >> 1) * 8;
                    int cl = nt * 8 + 2 * lr4 + (idx & 1);
                    int pwl = rl - cl + 63;
                    bool sel = ck ? (pwl >= 40) : (pwl < 40);
                    if (sel) s[nt][idx] += PW[rl * 44 + pwl - roff];
                }
            __syncwarp();
        }

        // ---- local row max -> RED ----
        float mx0 = -1e30f, mx1 = -1e30f;
#pragma unroll
        for (int nt = 0; nt < 8; nt++) {
            mx0 = fmaxf(mx0, fmaxf(s[nt][0], s[nt][1]));
            mx1 = fmaxf(mx1, fmaxf(s[nt][2], s[nt][3]));
        }
        mx0 = fmaxf(mx0, __shfl_xor_sync(0xffffffffu, mx0, 1));
        mx0 = fmaxf(mx0, __shfl_xor_sync(0xffffffffu, mx0, 2));
        mx1 = fmaxf(mx1, __shfl_xor_sync(0xffffffffu, mx1, 1));
        mx1 = fmaxf(mx1, __shfl_xor_sync(0xffffffffu, mx1, 2));
        if (lr4 == 0) {
            REDf[(wr * 16 + lq) * 2 + wc] = mx0;
            REDf[(wr * 16 + lq + 8) * 2 + wc] = mx1;
        }
        __syncthreads();                   // PST dead + RED visible
        if (jt < 7) loadE(j0 + 128);

        // ---- softmax finalize (m_new shared across col-halves) ----
#pragma unroll
        for (int h2 = 0; h2 < 2; h2++) {
            int row = wr * 16 + lq + h2 * 8;
            float mo = fmaxf(REDf[row * 2], REDf[row * 2 + 1]);
            float m_new = fmaxf(m_run[h2], mo);
            float scl = __expf(m_run[h2] - m_new);
            m_run[h2] = m_new;
            float rs = 0.f;
#pragma unroll
            for (int nt = 0; nt < 8; nt++) {
                float e0 = __expf(s[nt][h2 * 2] - m_new);
                float e1 = __expf(s[nt][h2 * 2 + 1] - m_new);
                s[nt][h2 * 2] = e0;
                s[nt][h2 * 2 + 1] = e1;
                rs += e0 + e1;
            }
            rs += __shfl_xor_sync(0xffffffffu, rs, 1);
            rs += __shfl_xor_sync(0xffffffffu, rs, 2);
            l_run[h2] = l_run[h2] * scl + rs;   // partial (own 64 cols)
#pragma unroll
            for (int nt = 0; nt < 4; nt++) {
                oacc[nt][h2 * 2] *= scl;
                oacc[nt][h2 * 2 + 1] *= scl;
            }
        }

        // ---- write p hi/lo tiles (own 16x64 region) ----
#pragma unroll
        for (int nt = 0; nt < 8; nt++)
#pragma unroll
            for (int h2 = 0; h2 < 2; h2++) {
                int row = wr * 16 + lq + h2 * 8;
                int c = wc * 64 + nt * 8 + 2 * lr4;
                float p0 = s[nt][h2 * 2], p1 = s[nt][h2 * 2 + 1];
                float h0 = __bfloat162float(__float2bfloat16(p0));
                float h1 = __bfloat162float(__float2bfloat16(p1));
                uint32_t off = row * 256 + (((c >> 3) ^ (row & 7)) << 4) + (c & 7) * 2;
                *(uint32_t*)(smc + O_PHI + off) = pack_bf16x2(p0, p1);
                *(uint32_t*)(smc + O_PLO + off) = pack_bf16x2(p0 - h0, p1 - h1);
            }

        if (jt < 7) cp_wait2(); else cp_wait0();   // V(jt) complete
        __syncthreads();                   // V + p visible to all

        // ---- PV (3-term split), output cols [wc*32, +32) ----
#pragma unroll
        for (int kk = 0; kk < 8; kk++) {
            uint32_t ah[4], al[4], vb[2][4];
            {
                uint32_t aoff = (wr * 16 + lrow) * 256 +
                    (((uint32_t)(2 * kk + lhalf) ^ (lrow & 7)) << 4);
                ldm_x4(ah, sb + O_PHI + aoff);
                ldm_x4(al, sb + O_PLO + aoff);
            }
            const uint32_t vrow = kk * 16 + lrow;
#pragma unroll
            for (int np = 0; np < 2; np++)
                ldm_x4t(vb[np], sb + O_VHI + vrow * 128 +
                        ((((uint32_t)(wc * 4 + np * 2 + lhalf)) ^ (lrow & 7)) << 4));
#pragma unroll
            for (int nt = 0; nt < 4; nt++)
                mma_bf16(oacc[nt], ah, vb[nt >> 1][(nt & 1) * 2],
                         vb[nt >> 1][(nt & 1) * 2 + 1]);
#pragma unroll
            for (int nt = 0; nt < 4; nt++)
                mma_bf16(oacc[nt], al, vb[nt >> 1][(nt & 1) * 2],
                         vb[nt >> 1][(nt & 1) * 2 + 1]);
#pragma unroll
            for (int np = 0; np < 2; np++)
                ldm_x4t(vb[np], sb + O_VLO + vrow * 128 +
                        ((((uint32_t)(wc * 4 + np * 2 + lhalf)) ^ (lrow & 7)) << 4));
#pragma unroll
            for (int nt = 0; nt < 4; nt++)
                mma_bf16(oacc[nt], ah, vb[nt >> 1][(nt & 1) * 2],
                         vb[nt >> 1][(nt & 1) * 2 + 1]);
        }
    }

    // ---- combine partial l across col-halves, normalize, write ----
    if (lr4 == 0) {
        REDf[(wr * 16 + lq) * 2 + wc] = l_run[0];
        REDf[(wr * 16 + lq + 8) * 2 + wc] = l_run[1];
    }
    __syncthreads();
#pragma unroll
    for (int h2 = 0; h2 < 2; h2++) {
        int row = wr * 16 + lq + h2 * 8;
        float inv = 1.f / (REDf[row * 2] + REDf[row * 2 + 1]);
        int rg = i0 + row;
#pragma unroll
        for (int nt = 0; nt < 4; nt++) {
            int d = wc * 32 + nt * 8 + 2 * lr4;
            *(float2*)(out + ((size_t)bb * NSEQ + rg) * DDIM + h * PDIM + d) =
                make_float2(oacc[nt][h2 * 2] * inv, oacc[nt][h2 * 2 + 1] * inv);
        }
    }
}

// ---------------------------------------------------------------------------
extern "C" void kernel_launch(void* const* d_in, const int* in_sizes, int n_in,
                              void* d_out, int out_size)
{
    const float* x  = (const float*)d_in[0];
    const float* wq = (const float*)d_in[1];
    const float* bq = (const float*)d_in[2];
    const float* wk = (const float*)d_in[3];
    const float* bk = (const float*)d_in[4];
    const float* wv = (const float*)d_in[5];
    const float* bv = (const float*)d_in[6];
    const float* de = (const float*)d_in[7];
    float* out = (float*)d_out;

    int B = in_sizes[0] / (NSEQ * DDIM);   // 8

    __nv_bfloat16 *xcat, *wcat, *qhi, *qlo, *khi, *klo, *vhi, *vlo, *ehi, *elo;
    cudaGetSymbolAddress((void**)&xcat, g_xcat);
    cudaGetSymbolAddress((void**)&wcat, g_wcat);
    cudaGetSymbolAddress((void**)&qhi, g_qhi);
    cudaGetSymbolAddress((void**)&qlo, g_qlo);
    cudaGetSymbolAddress((void**)&khi, g_khi);
    cudaGetSymbolAddress((void**)&klo, g_klo);
    cudaGetSymbolAddress((void**)&vhi, g_vhi);
    cudaGetSymbolAddress((void**)&vlo, g_vlo);
    cudaGetSymbolAddress((void**)&ehi, g_ehi);
    cudaGetSymbolAddress((void**)&elo, g_elo);

    cudaFuncSetAttribute(gemm_kernel,
                         cudaFuncAttributeMaxDynamicSharedMemorySize, GEMM_SMEM);
    cudaFuncSetAttribute(attn_kernel,
                         cudaFuncAttributeMaxDynamicSharedMemorySize, ATTN_SMEM);

    int nx4 = B * NSEQ * (DDIM / 4);
    int nw4 = DDIM * (DDIM / 4);
    xsplit_kernel<<<(nx4 + 255) / 256, 256>>>(x, xcat, nx4);
    dim3 gw((nw4 + 255) / 256, 3);
    wsplit_kernel<<<gw, 256>>>(wq, wk, wv, wcat);
    esplit_kernel<<<128, 256>>>(de, ehi, elo);

    dim3 g1(B * NSEQ / 128, DDIM / 128, 3);
    gemm_kernel<<<g1, 256, GEMM_SMEM>>>(xcat, wcat, bq, bk, bv,
                                        qhi, qlo, khi, klo, vhi, vlo);

    dim3 g2(NSEQ / 128, HNUM, B);
    attn_kernel<<<g2, 512, ATTN_SMEM>>>(qhi, qlo, khi, klo, vhi, vlo,
                                        ehi, elo, out);
}